// round 15
// baseline (speedup 1.0000x reference)
#include <cuda_runtime.h>
#include <cstdint>

// TSK fuzzy system via mma.sync tf32 tensor ops (baseline sm_80+ ISA).
// out[n] = sum_r fg_bar[n,r]*(x[n]·W[r]+b[r]); fg_bar separable-normalized.
// Pipeline: mg_prep (memberships once) -> b_prep (B fragments once, 4MB table)
// -> main (FG gen in regs + HMMA, B via one LDG.128 per k-tile) -> reduce -> out.

#define NSAMP 1024
#define NGROUP 128   // rule groups of 512
#define TILES 8      // sample tiles of 128

typedef unsigned long long ull;

__device__ float g_mg[NSAMP * 32];              // normalized memberships [n][m*4+j]
__device__ uint4 g_Bfrag[NGROUP * 2048];        // [g][kt*32+lane] = {bf0.xy, bf1.xy}
__device__ float g_part[NGROUP * 9 * NSAMP];    // [g][k][n]
__device__ float g_A[9 * NSAMP];                // [k][n] reduced

__device__ __forceinline__ uint32_t tf32r(float f) {
    uint32_t r; asm("cvt.rna.tf32.f32 %0, %1;" : "=r"(r) : "f"(f)); return r;
}
__device__ __forceinline__ ull pack2f(float a, float b) {
    ull r; asm("mov.b64 %0, {%1, %2};" : "=l"(r) : "f"(a), "f"(b)); return r;
}
__device__ __forceinline__ ull mul2(ull a, ull b) {
    ull d; asm("mul.rn.f32x2 %0, %1, %2;" : "=l"(d) : "l"(a), "l"(b)); return d;
}
__device__ __forceinline__ void unpack2u(ull v, uint32_t& a, uint32_t& b) {
    asm("mov.b64 {%0, %1}, %2;" : "=r"(a), "=r"(b) : "l"(v));
}
__device__ __forceinline__ void mma8(float* d, uint32_t a0, uint32_t a1,
                                     uint32_t a2, uint32_t a3,
                                     uint32_t b0, uint32_t b1) {
    asm volatile(
        "mma.sync.aligned.m16n8k8.row.col.f32.tf32.tf32.f32 "
        "{%0,%1,%2,%3}, {%4,%5,%6,%7}, {%8,%9}, {%0,%1,%2,%3};"
        : "+f"(d[0]), "+f"(d[1]), "+f"(d[2]), "+f"(d[3])
        : "r"(a0), "r"(a1), "r"(a2), "r"(a3), "r"(b0), "r"(b1));
}

// ---- prep 1: normalized memberships (once for all groups) ----
// 2048 threads, 2 per sample (4 dims each).
__global__ __launch_bounds__(256) void mg_prep(
    const float* __restrict__ x, const float* __restrict__ center,
    const float* __restrict__ sigma)
{
    int tid = threadIdx.x;
    int s = blockIdx.x * 128 + (tid & 127);
    int mh = tid >> 7;
    float4 xv4 = *reinterpret_cast<const float4*>(x + s * 8 + mh * 4);
    float xv[4] = {xv4.x, xv4.y, xv4.z, xv4.w};
#pragma unroll
    for (int mm = 0; mm < 4; mm++) {
        int m = mh * 4 + mm;
        float e[4], sum = 0.f;
#pragma unroll
        for (int j = 0; j < 4; j++) {
            float d = xv[mm] - center[m * 4 + j];
            float sg = sigma[m * 4 + j];
            e[j] = __expf(-0.5f * d * d * sg * sg);
            sum += e[j];
        }
        float inv = 1.0f / sum;
        float4 o = make_float4(e[0] * inv, e[1] * inv, e[2] * inv, e[3] * inv);
        *reinterpret_cast<float4*>(&g_mg[s * 32 + m * 4]) = o;
    }
}

// ---- prep 2: B fragments, one CTA per rule group ----
// g_Bfrag[gy*2048 + kt*32 + l] = {tf32 Wb[k0][n0], Wb[k0+4][n0],
//                                 Wb[k0][8+n0], Wb[k0+4][8+n0]},
// k0 = kt*8 + (l&3), n0 = l>>2; Wb[r] = [W[r][0..7], b[r], 0...].
__global__ __launch_bounds__(256) void b_prep(const float* __restrict__ W,
                                              const float* __restrict__ b)
{
    __shared__ float ws[512 * 9];
    int tid = threadIdx.x, gy = blockIdx.x;
    const float4* Wg4 = reinterpret_cast<const float4*>(W + (size_t)gy * 4096);
#pragma unroll
    for (int i = 0; i < 4; i++) {
        int fi = tid + i * 256;
        float4 v = Wg4[fi];
        int r = fi >> 1, h = fi & 1;
        float* row = ws + r * 9 + h * 4;
        row[0] = v.x; row[1] = v.y; row[2] = v.z; row[3] = v.w;
    }
    {
        float2 bv = reinterpret_cast<const float2*>(b + (size_t)gy * 512)[tid];
        ws[(2 * tid) * 9 + 8] = bv.x;
        ws[(2 * tid + 1) * 9 + 8] = bv.y;
    }
    __syncthreads();
#pragma unroll
    for (int e = 0; e < 8; e++) {
        int idx = tid + e * 256;
        int kt = idx >> 5, l = idx & 31;
        int n0 = l >> 2, k0 = kt * 8 + (l & 3);
        uint4 o;
        o.x = tf32r(ws[k0 * 9 + n0]);
        o.y = tf32r(ws[(k0 + 4) * 9 + n0]);
        o.z = (n0 == 0) ? tf32r(ws[k0 * 9 + 8]) : 0u;
        o.w = (n0 == 0) ? tf32r(ws[(k0 + 4) * 9 + 8]) : 0u;
        g_Bfrag[gy * 2048 + idx] = o;
    }
}

// ---- main: 256 thr = 8 warps, warp owns one 16-row m-tile ----
__global__ __launch_bounds__(256) void tsk_kernel()
{
    __shared__ float s_mg[128 * 36];   // padded to 36 for aligned STS.128

    int tid = threadIdx.x, lane = tid & 31, w = tid >> 5;
    int gy = blockIdx.y, tile = blockIdx.x;

    // prologue: coalesced copy of this tile's memberships into padded smem
    {
        const float4* src = reinterpret_cast<const float4*>(g_mg + tile * 128 * 32);
#pragma unroll
        for (int i = 0; i < 4; i++) {
            int fi = tid + i * 256;            // 1024 float4
            float4 v = src[fi];
            int s = fi >> 3, c4 = fi & 7;
            *reinterpret_cast<float4*>(&s_mg[s * 36 + c4 * 4]) = v;
        }
    }
    __syncthreads();

    // per-thread state: lane samples srow = lane/4 and srow+8; j7 = lane&3
    int srow = lane >> 2, j7 = lane & 3;
    const float* r0 = s_mg + (w * 16 + srow) * 36;
    const float* r1 = r0 + 8 * 36;

    int j0 = (gy >> 5) & 3, j1 = (gy >> 3) & 3, j2 = (gy >> 1) & 3;
    float pA = r0[j0] * r0[4 + j1] * r0[8 + j2] * r0[28 + j7];
    float pB = r1[j0] * r1[4 + j1] * r1[8 + j2] * r1[28 + j7];
    ull pre = pack2f(pA, pB);

    int j3b = (gy & 1) << 1;
    ull pm3[2], pm4[4], pm5[4], pm6[4];
#pragma unroll
    for (int t = 0; t < 2; t++) pm3[t] = pack2f(r0[12 + j3b + t], r1[12 + j3b + t]);
#pragma unroll
    for (int j = 0; j < 4; j++) {
        pm4[j] = pack2f(r0[16 + j], r1[16 + j]);
        pm5[j] = pack2f(r0[20 + j], r1[20 + j]);
        pm6[j] = pack2f(r0[24 + j], r1[24 + j]);
    }

    float d00[4] = {0,0,0,0};   // n-tile0 (W cols 0-7)
    float d01[4] = {0,0,0,0};   // n-tile1 (bias col 8)

    const uint4* Bp = g_Bfrag + gy * 2048 + lane;

    // mainloop: 64 k-tiles; per k-tile: 1 LDG.128 + 2 mul2 + 2 HMMA
#pragma unroll 1
    for (int t3 = 0; t3 < 2; t3++) {
        ull b3 = mul2(pre, pm3[t3]);
#pragma unroll
        for (int t4 = 0; t4 < 4; t4++) {
            ull b4 = mul2(b3, pm4[t4]);
            const uint4* Bt = Bp + (t3 * 32 + t4 * 8) * 32;
#pragma unroll
            for (int t5 = 0; t5 < 4; t5++) {
                ull b5 = mul2(b4, pm5[t5]);
#pragma unroll
                for (int t6 = 0; t6 < 2; t6++) {
                    uint4 bf = Bt[(t5 * 2 + t6) * 32];
                    ull alo = mul2(b5, pm6[2 * t6]);
                    ull ahi = mul2(b5, pm6[2 * t6 + 1]);
                    uint32_t a0, a1, a2, a3;
                    unpack2u(alo, a0, a1);
                    unpack2u(ahi, a2, a3);
                    mma8(d00, a0, a1, a2, a3, bf.x, bf.y);
                    mma8(d01, a0, a1, a2, a3, bf.z, bf.w);
                }
            }
        }
    }

    // write partials: g_part[(gy*9+k)*NSAMP + n]
    {
        int k0 = j7 * 2;
        int n0 = tile * 128 + w * 16 + srow;
        float* gp = g_part + (size_t)gy * 9 * NSAMP;
        gp[(k0 + 0) * NSAMP + n0]     = d00[0];
        gp[(k0 + 1) * NSAMP + n0]     = d00[1];
        gp[(k0 + 0) * NSAMP + n0 + 8] = d00[2];
        gp[(k0 + 1) * NSAMP + n0 + 8] = d00[3];
        if (j7 == 0) {   // bias column
            gp[8 * NSAMP + n0]     = d01[0];
            gp[8 * NSAMP + n0 + 8] = d01[2];
        }
    }
}

// ---- reduce: A[k][n] = sum_g g_part[g][k][n]; one thread per (k,n) ----
__global__ __launch_bounds__(256) void reduce_kernel() {
    int id = blockIdx.x * 256 + threadIdx.x;
    const float* p = g_part + id;
    float a0 = 0.f, a1 = 0.f, a2 = 0.f, a3 = 0.f;
    float a4 = 0.f, a5 = 0.f, a6 = 0.f, a7 = 0.f;
    const int stride = 9 * NSAMP;
#pragma unroll 2
    for (int g = 0; g < NGROUP; g += 8) {
        a0 += p[(g + 0) * stride];
        a1 += p[(g + 1) * stride];
        a2 += p[(g + 2) * stride];
        a3 += p[(g + 3) * stride];
        a4 += p[(g + 4) * stride];
        a5 += p[(g + 5) * stride];
        a6 += p[(g + 6) * stride];
        a7 += p[(g + 7) * stride];
    }
    g_A[id] = ((a0 + a1) + (a2 + a3)) + ((a4 + a5) + (a6 + a7));
}

// ---- out[n] = x[n]·A[:,n] + c[n] ----
__global__ __launch_bounds__(256) void out_kernel(const float* __restrict__ x,
                                                  float* __restrict__ out) {
    int n = blockIdx.x * 256 + threadIdx.x;
    float o = g_A[8 * NSAMP + n];
#pragma unroll
    for (int m = 0; m < 8; m++) o = fmaf(x[n * 8 + m], g_A[m * NSAMP + n], o);
    out[n] = o;
}

extern "C" void kernel_launch(void* const* d_in, const int* in_sizes, int n_in,
                              void* d_out, int out_size) {
    const float* x      = (const float*)d_in[0];
    const float* center = (const float*)d_in[1];
    const float* sigma  = (const float*)d_in[2];
    const float* W      = (const float*)d_in[3];
    const float* b      = (const float*)d_in[4];
    float* out = (float*)d_out;

    mg_prep<<<8, 256>>>(x, center, sigma);
    b_prep<<<NGROUP, 256>>>(W, b);
    dim3 grid(TILES, NGROUP);
    tsk_kernel<<<grid, 256>>>();
    reduce_kernel<<<(9 * NSAMP) / 256, 256>>>();
    out_kernel<<<NSAMP / 256, 256>>>(x, out);
}

// round 16
// speedup vs baseline: 1.1301x; 1.1301x over previous
#include <cuda_runtime.h>
#include <cstdint>

// TSK fuzzy system via mma.sync tf32 tensor ops (baseline sm_80+ ISA).
// out[n] = sum_r fg_bar[n,r]*(x[n]·W[r]+b[r]); fg_bar separable-normalized.
// Pipeline: prep (memberships + B-fragment table, one kernel) ->
// main (FG gen in regs + HMMA, B via one LDG.128 per k-tile) ->
// reduce (split-g, 4 chunks) -> out (combine chunks + final dot).

#define NSAMP 1024
#define NGROUP 128   // rule groups of 512
#define TILES 8      // sample tiles of 128

typedef unsigned long long ull;

__device__ float g_mg[NSAMP * 32];              // normalized memberships [n][m*4+j]
__device__ uint4 g_Bfrag[NGROUP * 2048];        // [g][kt*32+lane] = {bf0.xy, bf1.xy}
__device__ float g_part[NGROUP * 9 * NSAMP];    // [g][k][n]
__device__ float g_A4[4 * 9 * NSAMP];           // [chunk][k][n]

__device__ __forceinline__ uint32_t tf32r(float f) {
    uint32_t r; asm("cvt.rna.tf32.f32 %0, %1;" : "=r"(r) : "f"(f)); return r;
}
__device__ __forceinline__ ull pack2f(float a, float b) {
    ull r; asm("mov.b64 %0, {%1, %2};" : "=l"(r) : "f"(a), "f"(b)); return r;
}
__device__ __forceinline__ ull mul2(ull a, ull b) {
    ull d; asm("mul.rn.f32x2 %0, %1, %2;" : "=l"(d) : "l"(a), "l"(b)); return d;
}
__device__ __forceinline__ void unpack2u(ull v, uint32_t& a, uint32_t& b) {
    asm("mov.b64 {%0, %1}, %2;" : "=r"(a), "=r"(b) : "l"(v));
}
__device__ __forceinline__ void mma8(float* d, uint32_t a0, uint32_t a1,
                                     uint32_t a2, uint32_t a3,
                                     uint32_t b0, uint32_t b1) {
    asm volatile(
        "mma.sync.aligned.m16n8k8.row.col.f32.tf32.tf32.f32 "
        "{%0,%1,%2,%3}, {%4,%5,%6,%7}, {%8,%9}, {%0,%1,%2,%3};"
        : "+f"(d[0]), "+f"(d[1]), "+f"(d[2]), "+f"(d[3])
        : "r"(a0), "r"(a1), "r"(a2), "r"(a3), "r"(b0), "r"(b1));
}

// ---- prep: CTAs 0-7 = memberships; CTAs 8-135 = B fragments ----
__global__ __launch_bounds__(256) void prep_kernel(
    const float* __restrict__ x, const float* __restrict__ center,
    const float* __restrict__ sigma, const float* __restrict__ W,
    const float* __restrict__ b)
{
    int tid = threadIdx.x;
    if (blockIdx.x < 8) {
        // memberships: 2 threads per sample (4 dims each)
        int s = blockIdx.x * 128 + (tid & 127);
        int mh = tid >> 7;
        float4 xv4 = *reinterpret_cast<const float4*>(x + s * 8 + mh * 4);
        float xv[4] = {xv4.x, xv4.y, xv4.z, xv4.w};
#pragma unroll
        for (int mm = 0; mm < 4; mm++) {
            int m = mh * 4 + mm;
            float e[4], sum = 0.f;
#pragma unroll
            for (int j = 0; j < 4; j++) {
                float d = xv[mm] - center[m * 4 + j];
                float sg = sigma[m * 4 + j];
                e[j] = __expf(-0.5f * d * d * sg * sg);
                sum += e[j];
            }
            float inv = 1.0f / sum;
            float4 o = make_float4(e[0] * inv, e[1] * inv, e[2] * inv, e[3] * inv);
            *reinterpret_cast<float4*>(&g_mg[s * 32 + m * 4]) = o;
        }
    } else {
        // B fragments, one CTA per rule group:
        // g_Bfrag[gy*2048 + kt*32 + l] = {tf32 Wb[k0][n0], Wb[k0+4][n0],
        //   Wb[k0][8], Wb[k0+4][8] (n0==0 only)}, k0 = kt*8+(l&3), n0 = l>>2
        __shared__ float ws[512 * 9];
        int gy = blockIdx.x - 8;
        const float4* Wg4 = reinterpret_cast<const float4*>(W + (size_t)gy * 4096);
#pragma unroll
        for (int i = 0; i < 4; i++) {
            int fi = tid + i * 256;
            float4 v = Wg4[fi];
            int r = fi >> 1, h = fi & 1;
            float* row = ws + r * 9 + h * 4;
            row[0] = v.x; row[1] = v.y; row[2] = v.z; row[3] = v.w;
        }
        {
            float2 bv = reinterpret_cast<const float2*>(b + (size_t)gy * 512)[tid];
            ws[(2 * tid) * 9 + 8] = bv.x;
            ws[(2 * tid + 1) * 9 + 8] = bv.y;
        }
        __syncthreads();
#pragma unroll
        for (int e = 0; e < 8; e++) {
            int idx = tid + e * 256;
            int kt = idx >> 5, l = idx & 31;
            int n0 = l >> 2, k0 = kt * 8 + (l & 3);
            uint4 o;
            o.x = tf32r(ws[k0 * 9 + n0]);
            o.y = tf32r(ws[(k0 + 4) * 9 + n0]);
            o.z = (n0 == 0) ? tf32r(ws[k0 * 9 + 8]) : 0u;
            o.w = (n0 == 0) ? tf32r(ws[(k0 + 4) * 9 + 8]) : 0u;
            g_Bfrag[gy * 2048 + idx] = o;
        }
    }
}

// ---- main: 256 thr = 8 warps, warp owns one 16-row m-tile ----
__global__ __launch_bounds__(256) void tsk_kernel()
{
    __shared__ float s_mg[128 * 36];   // padded to 36 for aligned STS.128

    int tid = threadIdx.x, lane = tid & 31, w = tid >> 5;
    int gy = blockIdx.y, tile = blockIdx.x;

    // prologue: coalesced copy of this tile's memberships into padded smem
    {
        const float4* src = reinterpret_cast<const float4*>(g_mg + tile * 128 * 32);
#pragma unroll
        for (int i = 0; i < 4; i++) {
            int fi = tid + i * 256;            // 1024 float4
            float4 v = src[fi];
            int s = fi >> 3, c4 = fi & 7;
            *reinterpret_cast<float4*>(&s_mg[s * 36 + c4 * 4]) = v;
        }
    }
    __syncthreads();

    // per-thread state: lane samples srow = lane/4 and srow+8; j7 = lane&3
    int srow = lane >> 2, j7 = lane & 3;
    const float* r0 = s_mg + (w * 16 + srow) * 36;
    const float* r1 = r0 + 8 * 36;

    int j0 = (gy >> 5) & 3, j1 = (gy >> 3) & 3, j2 = (gy >> 1) & 3;
    float pA = r0[j0] * r0[4 + j1] * r0[8 + j2] * r0[28 + j7];
    float pB = r1[j0] * r1[4 + j1] * r1[8 + j2] * r1[28 + j7];
    ull pre = pack2f(pA, pB);

    int j3b = (gy & 1) << 1;
    ull pm3[2], pm4[4], pm5[4], pm6[4];
#pragma unroll
    for (int t = 0; t < 2; t++) pm3[t] = pack2f(r0[12 + j3b + t], r1[12 + j3b + t]);
#pragma unroll
    for (int j = 0; j < 4; j++) {
        pm4[j] = pack2f(r0[16 + j], r1[16 + j]);
        pm5[j] = pack2f(r0[20 + j], r1[20 + j]);
        pm6[j] = pack2f(r0[24 + j], r1[24 + j]);
    }

    float d00[4] = {0,0,0,0};   // n-tile0 (W cols 0-7)
    float d01[4] = {0,0,0,0};   // n-tile1 (bias col 8)

    const uint4* Bp = g_Bfrag + gy * 2048 + lane;

    // mainloop: 64 k-tiles; per k-tile: 1 LDG.128 + 2 mul2 + 2 HMMA
#pragma unroll 1
    for (int t3 = 0; t3 < 2; t3++) {
        ull b3 = mul2(pre, pm3[t3]);
#pragma unroll
        for (int t4 = 0; t4 < 4; t4++) {
            ull b4 = mul2(b3, pm4[t4]);
            const uint4* Bt = Bp + (t3 * 32 + t4 * 8) * 32;
#pragma unroll
            for (int t5 = 0; t5 < 4; t5++) {
                ull b5 = mul2(b4, pm5[t5]);
#pragma unroll
                for (int t6 = 0; t6 < 2; t6++) {
                    uint4 bf = Bt[(t5 * 2 + t6) * 32];
                    ull alo = mul2(b5, pm6[2 * t6]);
                    ull ahi = mul2(b5, pm6[2 * t6 + 1]);
                    uint32_t a0, a1, a2, a3;
                    unpack2u(alo, a0, a1);
                    unpack2u(ahi, a2, a3);
                    mma8(d00, a0, a1, a2, a3, bf.x, bf.y);
                    mma8(d01, a0, a1, a2, a3, bf.z, bf.w);
                }
            }
        }
    }

    // write partials: g_part[(gy*9+k)*NSAMP + n]
    {
        int k0 = j7 * 2;
        int n0 = tile * 128 + w * 16 + srow;
        float* gp = g_part + (size_t)gy * 9 * NSAMP;
        gp[(k0 + 0) * NSAMP + n0]     = d00[0];
        gp[(k0 + 1) * NSAMP + n0]     = d00[1];
        gp[(k0 + 0) * NSAMP + n0 + 8] = d00[2];
        gp[(k0 + 1) * NSAMP + n0 + 8] = d00[3];
        if (j7 == 0) {   // bias column
            gp[8 * NSAMP + n0]     = d01[0];
            gp[8 * NSAMP + n0 + 8] = d01[2];
        }
    }
}

// ---- reduce: split-g. chunk c sums groups [c*32, c*32+32) ----
// grid (36, 4); thread handles one (k,n) item for its chunk.
__global__ __launch_bounds__(256) void reduce_kernel() {
    int id = blockIdx.x * 256 + threadIdx.x;   // id = k*NSAMP + n
    int c = blockIdx.y;
    const int stride = 9 * NSAMP;
    const float* p = g_part + (size_t)c * 32 * stride + id;
    float a0 = 0.f, a1 = 0.f, a2 = 0.f, a3 = 0.f;
    float a4 = 0.f, a5 = 0.f, a6 = 0.f, a7 = 0.f;
#pragma unroll
    for (int g = 0; g < 32; g += 8) {
        a0 += p[(g + 0) * stride];
        a1 += p[(g + 1) * stride];
        a2 += p[(g + 2) * stride];
        a3 += p[(g + 3) * stride];
        a4 += p[(g + 4) * stride];
        a5 += p[(g + 5) * stride];
        a6 += p[(g + 6) * stride];
        a7 += p[(g + 7) * stride];
    }
    g_A4[c * stride + id] = ((a0 + a1) + (a2 + a3)) + ((a4 + a5) + (a6 + a7));
}

// ---- out[n] = x[n]·A[:,n] + c[n], A = sum of 4 chunks ----
__global__ __launch_bounds__(256) void out_kernel(const float* __restrict__ x,
                                                  float* __restrict__ out) {
    int n = blockIdx.x * 256 + threadIdx.x;
    const int stride = 9 * NSAMP;
    float A[9];
#pragma unroll
    for (int k = 0; k < 9; k++) {
        A[k] = (g_A4[0 * stride + k * NSAMP + n] + g_A4[1 * stride + k * NSAMP + n])
             + (g_A4[2 * stride + k * NSAMP + n] + g_A4[3 * stride + k * NSAMP + n]);
    }
    float o = A[8];
#pragma unroll
    for (int m = 0; m < 8; m++) o = fmaf(x[n * 8 + m], A[m], o);
    out[n] = o;
}

extern "C" void kernel_launch(void* const* d_in, const int* in_sizes, int n_in,
                              void* d_out, int out_size) {
    const float* x      = (const float*)d_in[0];
    const float* center = (const float*)d_in[1];
    const float* sigma  = (const float*)d_in[2];
    const float* W      = (const float*)d_in[3];
    const float* b      = (const float*)d_in[4];
    float* out = (float*)d_out;

    prep_kernel<<<8 + NGROUP, 256>>>(x, center, sigma, W, b);
    dim3 grid(TILES, NGROUP);
    tsk_kernel<<<grid, 256>>>();
    dim3 rgrid(36, 4);
    reduce_kernel<<<rgrid, 256>>>();
    out_kernel<<<NSAMP / 256, 256>>>(x, out);
}